// round 1
// baseline (speedup 1.0000x reference)
#include <cuda_runtime.h>
#include <cstdint>

#define B_  64
#define T_  2048
#define I_  256
#define H_  256
#define G3_ 768

// 402 MB scratch for precomputed input gates: layout [t][b][768]
__device__ float g_Gi[(size_t)B_ * T_ * G3_];

// ======================= Phase 1: Gi = x @ W_ih^T + b_ih =======================
#define BM 128
#define BN 64
#define BK 32
#define PAD 36

__global__ __launch_bounds__(256) void gi_gemm(
    const float* __restrict__ x, const float* __restrict__ W_ih,
    const float* __restrict__ b_ih, const int* __restrict__ lengths)
{
    const int m0    = blockIdx.x * BM;        // row = b*T + t
    const int batch = m0 >> 11;               // 2048 rows per batch, 128 | 2048
    const int t0    = m0 & (T_ - 1);
    if (t0 >= __ldg(&lengths[batch])) return; // whole tile masked -> skip
    const int n0 = blockIdx.y * BN;

    __shared__ float As[BM][PAD];
    __shared__ float Bs[BN][PAD];

    const int tid = threadIdx.x;
    const int tx = tid & 15, ty = tid >> 4;   // 16 x 16 -> thread tile 8(m) x 4(n)

    float acc[8][4];
#pragma unroll
    for (int i = 0; i < 8; i++)
#pragma unroll
        for (int c = 0; c < 4; c++) acc[i][c] = 0.f;

    for (int kt = 0; kt < I_; kt += BK) {
        // A tile: 128x32 floats = 1024 float4, 4 per thread
#pragma unroll
        for (int j = 0; j < 4; j++) {
            int idx = tid + j * 256;
            int row = idx >> 3, kp = idx & 7;
            float4 v = *(const float4*)&x[(size_t)(m0 + row) * I_ + kt + kp * 4];
            *(float4*)&As[row][kp * 4] = v;
        }
        // B tile: 64x32 floats = 512 float4, 2 per thread
#pragma unroll
        for (int j = 0; j < 2; j++) {
            int idx = tid + j * 256;
            int row = idx >> 3, kp = idx & 7;
            float4 v = *(const float4*)&W_ih[(size_t)(n0 + row) * I_ + kt + kp * 4];
            *(float4*)&Bs[row][kp * 4] = v;
        }
        __syncthreads();
#pragma unroll
        for (int k = 0; k < BK; k++) {
            float a[8], b[4];
#pragma unroll
            for (int i = 0; i < 8; i++) a[i] = As[ty * 8 + i][k];
#pragma unroll
            for (int c = 0; c < 4; c++) b[c] = Bs[tx * 4 + c][k];
#pragma unroll
            for (int i = 0; i < 8; i++)
#pragma unroll
                for (int c = 0; c < 4; c++) acc[i][c] += a[i] * b[c];
        }
        __syncthreads();
    }

#pragma unroll
    for (int i = 0; i < 8; i++) {
        int t = t0 + ty * 8 + i;
        int n = n0 + tx * 4;
        float4 v;
        v.x = acc[i][0] + b_ih[n + 0];
        v.y = acc[i][1] + b_ih[n + 1];
        v.z = acc[i][2] + b_ih[n + 2];
        v.w = acc[i][3] + b_ih[n + 3];
        *(float4*)&g_Gi[((size_t)t * B_ + batch) * G3_ + n] = v;
    }
}

// ======================= Phase 2: recurrence =======================
// 32 clusters of 4 CTAs. Cluster c handles batches {2c, 2c+1}.
// CTA rank r owns H-columns [r*64, r*64+64): W_hh rows {g*256 + r*64 + j}.
// W slice (192 rows x 256) lives in SMEM in thread-major float4 layout.
// h (2 batches x 256) is replicated in every CTA's SMEM, double-buffered,
// updated slice-wise via DSMEM stores + one cluster barrier per step.

#define REC_THREADS 768
#define SMEM_W_BYTES   (16 * 768 * 16)          // 196608: Wq[16][768] float4
#define SMEM_H_BYTES   (2 * 2 * 64 * 16)        // 4096:  hb[2][2][64] float4
#define SMEM_GH_BYTES  (2 * 192 * 4)            // 1536:  ghsh[2][192]
#define SMEM_REC_BYTES (SMEM_W_BYTES + SMEM_H_BYTES + SMEM_GH_BYTES)

__device__ __forceinline__ float sigm(float v) { return 1.f / (1.f + __expf(-v)); }

__global__ void __cluster_dims__(4, 1, 1) __launch_bounds__(REC_THREADS, 1)
gru_rec(const float* __restrict__ att, const int* __restrict__ lengths,
        const float* __restrict__ W_hh, const float* __restrict__ b_hh,
        float* __restrict__ out)
{
    extern __shared__ char smem_raw[];
    float4* Wq   = (float4*)smem_raw;                                  // [16][768]
    float4* hb   = (float4*)(smem_raw + SMEM_W_BYTES);                 // [buf][b][64]
    float*  ghsh = (float*)(smem_raw + SMEM_W_BYTES + SMEM_H_BYTES);   // [b][192]

    uint32_t rank;
    asm("mov.u32 %0, %%cluster_ctarank;" : "=r"(rank));
    const int cid = blockIdx.x >> 2;
    const int b0  = cid * 2;

    const int tid = threadIdx.x;
    const int rr = tid >> 2;           // 0..191 : (gate g = rr/64, col j = rr%64)
    const int kq = tid & 3;            // k-quarter: k in [kq*64, kq*64+64)

    // ---- load W slice: Wq[i*768 + tid] = W_hh[grow][kq*64 + 4i .. +3] ----
    const int grow = (rr >> 6) * 256 + (int)rank * 64 + (rr & 63);
#pragma unroll
    for (int i = 0; i < 16; i++)
        Wq[i * 768 + tid] = *(const float4*)&W_hh[(size_t)grow * H_ + kq * 64 + i * 4];

    // ---- zero h buffer 0 (both batches, full 256 cols) ----
    if (tid < 128) hb[(tid >> 6) * 64 + (tid & 63)] = make_float4(0.f, 0.f, 0.f, 0.f);

    // ---- gate-thread constants (threads 0..127: b=tid/64, j=tid%64) ----
    const int gb  = tid >> 6;
    const int gj  = tid & 63;
    const int col = (int)rank * 64 + gj;
    const int myb = b0 + gb;
    float bhr = 0.f, bhz = 0.f, bhn = 0.f;
    int mylen = 0;
    if (tid < 128) {
        bhr = b_hh[col];
        bhz = b_hh[256 + col];
        bhn = b_hh[512 + col];
        mylen = lengths[myb];
    }
    const int Tmax = max(__ldg(&lengths[b0]), __ldg(&lengths[b0 + 1]));
    // interleaved float index of column `col` inside hb[buf][b]
    const int fidx = ((gj >> 2) * 4 + (int)rank) * 4 + (gj & 3);

    __syncthreads();

    for (int t = 0; t < Tmax; t++) {
        const int cur = t & 1, nxt = cur ^ 1;

        // prefetch gi + attention weight (consumed ~1.5k cycles later)
        float gir = 0.f, giz = 0.f, gin = 0.f, wt = 0.f;
        if (tid < 128) {
            const size_t base = ((size_t)t * B_ + myb) * G3_;
            gir = __ldg(&g_Gi[base + col]);
            giz = __ldg(&g_Gi[base + 256 + col]);
            gin = __ldg(&g_Gi[base + 512 + col]);
            wt  = __ldg(&att[(size_t)myb * T_ + t]);
        }

        // ---- matvec: partial dot for (row rr, k-quarter kq), both batches ----
        const float4* h0p = hb + (cur * 2 + 0) * 64;
        const float4* h1p = hb + (cur * 2 + 1) * 64;
        float a0 = 0.f, a1 = 0.f, a2 = 0.f, a3 = 0.f;
#pragma unroll
        for (int i = 0; i < 16; i += 2) {
            float4 w  = Wq[i * 768 + tid];
            float4 w2 = Wq[(i + 1) * 768 + tid];
            float4 p  = h0p[i * 4 + kq];
            float4 q  = h1p[i * 4 + kq];
            float4 p2 = h0p[(i + 1) * 4 + kq];
            float4 q2 = h1p[(i + 1) * 4 + kq];
            a0 += w.x  * p.x  + w.y  * p.y  + w.z  * p.z  + w.w  * p.w;
            a1 += w.x  * q.x  + w.y  * q.y  + w.z  * q.z  + w.w  * q.w;
            a2 += w2.x * p2.x + w2.y * p2.y + w2.z * p2.z + w2.w * p2.w;
            a3 += w2.x * q2.x + w2.y * q2.y + w2.z * q2.z + w2.w * q2.w;
        }
        float s0 = a0 + a2, s1 = a1 + a3;
        s0 += __shfl_xor_sync(0xffffffffu, s0, 1);
        s0 += __shfl_xor_sync(0xffffffffu, s0, 2);
        s1 += __shfl_xor_sync(0xffffffffu, s1, 1);
        s1 += __shfl_xor_sync(0xffffffffu, s1, 2);
        if (kq == 0) { ghsh[rr] = s0; ghsh[192 + rr] = s1; }
        __syncthreads();

        // ---- gates + broadcast h slice to all 4 CTAs ----
        if (tid < 128) {
            const float* gsh = ghsh + gb * 192;
            const float ghr = gsh[gj], ghz = gsh[64 + gj], ghn = gsh[128 + gj];
            const float hprev = ((const float*)(hb + (cur * 2 + gb) * 64))[fidx];
            const float r = sigm(gir + ghr + bhr);
            const float z = sigm(giz + ghz + bhz);
            const float n = tanhf(gin + r * (ghn + bhn));
            const float hnew = (1.f - z) * n + z * hprev;
            const float hg   = wt * hnew + (1.f - wt) * hprev;
            const float hv   = (t < mylen) ? hg : hprev;

            uint32_t laddr = (uint32_t)__cvta_generic_to_shared(
                (const void*)(((float*)(hb + (nxt * 2 + gb) * 64)) + fidx));
#pragma unroll
            for (int rdst = 0; rdst < 4; rdst++) {
                uint32_t raddr;
                asm volatile("mapa.shared::cluster.u32 %0, %1, %2;"
                             : "=r"(raddr) : "r"(laddr), "r"(rdst));
                asm volatile("st.shared::cluster.f32 [%0], %1;"
                             :: "r"(raddr), "f"(hv) : "memory");
            }
        }

        // one cluster barrier per step (release/acquire orders DSMEM stores)
        asm volatile("barrier.cluster.arrive.aligned;" ::: "memory");
        asm volatile("barrier.cluster.wait.aligned;" ::: "memory");
    }

    if (tid < 128) {
        const float hfin = ((const float*)(hb + ((Tmax & 1) * 2 + gb) * 64))[fidx];
        out[(size_t)myb * H_ + col] = hfin;
    }
}

// ======================= launch =======================
extern "C" void kernel_launch(void* const* d_in, const int* in_sizes, int n_in,
                              void* d_out, int out_size)
{
    const float* x       = (const float*)d_in[0];
    const float* att     = (const float*)d_in[1];
    const int*   lengths = (const int*)  d_in[2];
    const float* W_ih    = (const float*)d_in[3];
    const float* W_hh    = (const float*)d_in[4];
    const float* b_ih    = (const float*)d_in[5];
    const float* b_hh    = (const float*)d_in[6];
    float* out = (float*)d_out;
    (void)in_sizes; (void)n_in; (void)out_size;

    cudaFuncSetAttribute(gru_rec, cudaFuncAttributeMaxDynamicSharedMemorySize,
                         SMEM_REC_BYTES);

    dim3 ggrid((B_ * T_) / BM, G3_ / BN);
    gi_gemm<<<ggrid, 256>>>(x, W_ih, b_ih, lengths);
    gru_rec<<<128, REC_THREADS, SMEM_REC_BYTES>>>(att, lengths, W_hh, b_hh, out);
}